// round 5
// baseline (speedup 1.0000x reference)
#include <cuda_runtime.h>

// RoIAlign, NCHW fp32, OUT 7x7, sampling_ratio 2, scale 0.25
// features: (2, 256, 200, 304), rois: (512, 5), out: (512, 256, 7, 7)
//
// Two-kernel scheme:
//   1) setup_kernel: 1 thread per ROI. Computes ALL geometry once (previously
//      recomputed by 64 warps/ROI): per-lane x-table (column, x-weight with
//      validity folded) and per-(roi,oy) row plan: up to 4 deduped feature rows
//      with merged weights (0.25 sample-mean and y-validity folded in). Unused
//      slots get weight 0 (skipped by warp-uniform tests in the main kernel).
//   2) main kernel: warp = (roi, 8 channels). Lanes 0..13 = corner x0 for
//      x-samples 0..13, lanes 16..29 = corner x0+1, others idle (wx=0).
//      Hot loop per oy: 2 uniform plan loads + batched single-row LDGs
//      (8 channels x 2..4 rows, MLP up to 32), FMA accumulate, then one
//      two-step shfl reduction and a predicated contiguous store.

namespace {
constexpr int OUT_H = 7;
constexpr int OUT_W = 7;
constexpr int C     = 256;
constexpr int H     = 200;
constexpr int W     = 304;
constexpr int R     = 512;
constexpr float SCALE = 0.25f;

constexpr int WARPS_PER_BLOCK = 8;
constexpr int GROUPS          = 4;                          // gridDim.y
constexpr int WARPS_PER_ROI   = WARPS_PER_BLOCK * GROUPS;   // 32
constexpr int CH_PER_WARP     = C / WARPS_PER_ROI;          // 8
constexpr int PLANE           = H * W;                      // 60800
}

// ---- scratch (written fully by setup_kernel on every launch) ----
__device__ float2 g_x[R][32];      // .x = __int_as_float(col), .y = wx
__device__ int4   g_off[R][OUT_H]; // row offsets (row*W), slots 0..3
__device__ float4 g_w[R][OUT_H];   // merged row weights, 0 => slot unused
__device__ int    g_b[R];          // batch index

__global__ void setup_kernel(const float* __restrict__ rois)
{
    int r = blockIdx.x * blockDim.x + threadIdx.x;
    if (r >= R) return;

    const float bf  = rois[r * 5 + 0];
    const float rx1 = rois[r * 5 + 1] * SCALE - 0.5f;
    const float ry1 = rois[r * 5 + 2] * SCALE - 0.5f;
    const float rx2 = rois[r * 5 + 3] * SCALE - 0.5f;
    const float ry2 = rois[r * 5 + 4] * SCALE - 0.5f;
    g_b[r] = (int)bf;

    const float bin_w = (rx2 - rx1) * (1.0f / OUT_W);
    const float bin_h = (ry2 - ry1) * (1.0f / OUT_H);

    // ---- x-table: 14 x-samples -> 32 lane entries ----
    for (int sx = 0; sx < 16; ++sx) {
        if (sx < 14) {
            float x  = rx1 + (float)(sx >> 1) * bin_w
                           + ((float)(sx & 1) + 0.5f) * bin_w * 0.5f;
            float vx = ((x > -1.0f) && (x < (float)W)) ? 1.0f : 0.0f;
            float xc = fminf(fmaxf(x, 0.0f), (float)(W - 1));
            int   x0 = (int)xc;
            float lx = xc - (float)x0;
            g_x[r][sx]      = make_float2(__int_as_float(x0), (1.0f - lx) * vx);
            g_x[r][16 + sx] = make_float2(__int_as_float(min(x0 + 1, W - 1)), lx * vx);
        } else {
            g_x[r][sx]      = make_float2(__int_as_float(0), 0.0f);
            g_x[r][16 + sx] = make_float2(__int_as_float(0), 0.0f);
        }
    }

    // ---- y row plans: per oy, merge the 4 (row, weight) candidates ----
    for (int oy = 0; oy < OUT_H; ++oy) {
        int   rows[4];
        float wts[4];
        int   n = 0;

        #pragma unroll
        for (int g = 0; g < 2; ++g) {
            float yg = ry1 + (float)oy * bin_h + (0.25f + 0.5f * (float)g) * bin_h;
            float vy = ((yg > -1.0f) && (yg < (float)H)) ? 1.0f : 0.0f;
            float yc = fminf(fmaxf(yg, 0.0f), (float)(H - 1));
            int   t  = (int)yc;
            float ly = yc - (float)t;
            int   bb = min(t + 1, H - 1);
            float wT = 0.25f * (1.0f - ly) * vy;
            float wB = 0.25f * ly * vy;

            int   cr[2] = { t, bb };
            float cw[2] = { wT, wB };
            #pragma unroll
            for (int k = 0; k < 2; ++k) {
                bool merged = false;
                for (int s = 0; s < n; ++s) {
                    if (rows[s] == cr[k]) { wts[s] += cw[k]; merged = true; break; }
                }
                if (!merged) { rows[n] = cr[k]; wts[n] = cw[k]; ++n; }
            }
        }
        for (int s = n; s < 4; ++s) { rows[s] = rows[0]; wts[s] = 0.0f; }

        g_off[r][oy] = make_int4(rows[0] * W, rows[1] * W, rows[2] * W, rows[3] * W);
        g_w[r][oy]   = make_float4(wts[0], wts[1], wts[2], wts[3]);
    }
}

__global__ __launch_bounds__(WARPS_PER_BLOCK * 32)
void roi_align_kernel(const float* __restrict__ feat,
                      float* __restrict__ out)
{
    const int r      = blockIdx.x;
    const int warpId = threadIdx.x >> 5;
    const int lane   = threadIdx.x & 31;
    const int wroi   = blockIdx.y * WARPS_PER_BLOCK + warpId;  // 0..31
    const int c0     = wroi * CH_PER_WARP;

    const int    b  = g_b[r];
    const float2 xe = g_x[r][lane];
    const int    col = __float_as_int(xe.x);
    const float  wx  = xe.y;

    const float* pb   = feat + ((size_t)b * C + c0) * PLANE + col;
    float*       outp = out + ((size_t)r * C + c0) * (OUT_H * OUT_W);

    #pragma unroll
    for (int oy = 0; oy < OUT_H; ++oy) {
        const int4   off = g_off[r][oy];   // warp-uniform
        const float4 w   = g_w[r][oy];     // warp-uniform

        float acc[CH_PER_WARP];

        // slots 0,1 always present (>=2 candidate rows per oy)
        #pragma unroll
        for (int cc = 0; cc < CH_PER_WARP; ++cc) {
            float v0 = __ldg(pb + (size_t)cc * PLANE + off.x);
            float v1 = __ldg(pb + (size_t)cc * PLANE + off.y);
            acc[cc] = w.x * v0 + w.y * v1;
        }
        if (w.z != 0.0f) {          // warp-uniform branch
            #pragma unroll
            for (int cc = 0; cc < CH_PER_WARP; ++cc)
                acc[cc] += w.z * __ldg(pb + (size_t)cc * PLANE + off.z);
        }
        if (w.w != 0.0f) {          // warp-uniform branch
            #pragma unroll
            for (int cc = 0; cc < CH_PER_WARP; ++cc)
                acc[cc] += w.w * __ldg(pb + (size_t)cc * PLANE + off.w);
        }

        #pragma unroll
        for (int cc = 0; cc < CH_PER_WARP; ++cc) {
            float v = wx * acc[cc];
            v += __shfl_down_sync(0xffffffffu, v, 16);  // sum corners x0 + x0+1
            v += __shfl_down_sync(0xffffffffu, v, 1);   // sum x-sample pairs
            if (lane < 14 && (lane & 1) == 0) {
                outp[(size_t)cc * (OUT_H * OUT_W) + oy * OUT_W + (lane >> 1)] = v;
            }
        }
    }
}

extern "C" void kernel_launch(void* const* d_in, const int* in_sizes, int n_in,
                              void* d_out, int out_size)
{
    const float* feat = (const float*)d_in[0];
    const float* rois = (const float*)d_in[1];
    float*       out  = (float*)d_out;

    setup_kernel<<<(R + 127) / 128, 128>>>(rois);

    dim3 grid(R, GROUPS);
    dim3 block(WARPS_PER_BLOCK * 32);
    roi_align_kernel<<<grid, block>>>(feat, out);
}

// round 6
// speedup vs baseline: 1.4703x; 1.4703x over previous
#include <cuda_runtime.h>

// RoIAlign, NCHW fp32, OUT 7x7, sampling_ratio 2, scale 0.25
// features: (2, 256, 200, 304), rois: (512, 5), out: (512, 256, 7, 7)
//
// Single kernel. Block = (roi, 32-channel group), 8 warps; warp = 4 channels.
// Block prologue precomputes the ROI plan into shared memory:
//   s_x[32]   : per-lane (column, x-weight) — lanes 0..13 corner x0,
//               lanes 16..29 corner x0+1, others weight 0
//   s_plan[14]: per y-sample (rowT*W, rowB*W, wT, wB) with 0.25 mean and
//               y-validity folded into the weights
//   s_code[14]: row-cache transition vs previous y-sample:
//               0 = both rows cached, 1 = shift (load bottom), 2 = load both
// Hot loop (R4's two-row register-cache walk, geometry-free): per y-sample
// one LDS.128 + warp-uniform transition branch + batched single-row LDGs
// (4 channels) + FMA; per oy one two-step shfl reduction + predicated store.

namespace {
constexpr int OUT_H = 7;
constexpr int OUT_W = 7;
constexpr int C     = 256;
constexpr int H     = 200;
constexpr int W     = 304;
constexpr int R     = 512;
constexpr float SCALE = 0.25f;

constexpr int WARPS_PER_BLOCK = 8;
constexpr int GROUPS          = 8;                          // gridDim.y
constexpr int WARPS_PER_ROI   = WARPS_PER_BLOCK * GROUPS;   // 64
constexpr int CH_PER_WARP     = C / WARPS_PER_ROI;          // 4
constexpr int PLANE           = H * W;                      // 60800
constexpr int NSAMP           = OUT_H * 2;                  // 14 y-samples
}

__global__ __launch_bounds__(WARPS_PER_BLOCK * 32)
void roi_align_kernel(const float* __restrict__ feat,
                      const float* __restrict__ rois,
                      float* __restrict__ out)
{
    __shared__ float2 s_x[32];        // per-lane (col as int bits, wx)
    __shared__ float4 s_plan[NSAMP];  // (offT bits, offB bits, wT, wB)
    __shared__ int    s_code[NSAMP];
    __shared__ int    s_b;

    const int r    = blockIdx.x;
    const int tid  = threadIdx.x;
    const int lane = tid & 31;

    // ---------- prologue: build the plan ----------
    if (tid < 64) {
        const float rx1 = rois[r * 5 + 1] * SCALE - 0.5f;
        const float ry1 = rois[r * 5 + 2] * SCALE - 0.5f;
        const float rx2 = rois[r * 5 + 3] * SCALE - 0.5f;
        const float ry2 = rois[r * 5 + 4] * SCALE - 0.5f;
        const float bin_w = (rx2 - rx1) * (1.0f / OUT_W);
        const float bin_h = (ry2 - ry1) * (1.0f / OUT_H);

        if (tid == 0) s_b = (int)rois[r * 5 + 0];

        if (tid < NSAMP) {
            // y-sample tid: oy = tid>>1, g = tid&1
            const int i = tid;
            float yg = ry1 + ((float)(i >> 1) + 0.25f + 0.5f * (float)(i & 1)) * bin_h;
            float vy = ((yg > -1.0f) && (yg < (float)H)) ? 1.0f : 0.0f;
            float yc = fminf(fmaxf(yg, 0.0f), (float)(H - 1));
            int   t  = (int)yc;
            float ly = yc - (float)t;
            int   bb = min(t + 1, H - 1);
            s_plan[i] = make_float4(__int_as_float(t * W), __int_as_float(bb * W),
                                    0.25f * (1.0f - ly) * vy, 0.25f * ly * vy);
            int code = 2;
            if (i > 0) {
                float ygp = ry1 + ((float)((i - 1) >> 1) + 0.25f + 0.5f * (float)((i - 1) & 1)) * bin_h;
                float ycp = fminf(fmaxf(ygp, 0.0f), (float)(H - 1));
                int   tp  = (int)ycp;
                int   bp  = min(tp + 1, H - 1);
                code = (t == tp) ? 0 : ((t == bp) ? 1 : 2);
            }
            s_code[i] = code;
        }

        if (tid >= 32) {
            // x-table entry l = tid - 32
            const int  l  = tid - 32;
            const int  sx = l & 15;
            const bool hi = l >= 16;
            float2 e = make_float2(__int_as_float(0), 0.0f);
            if (sx < 14) {
                float x  = rx1 + ((float)(sx >> 1) + ((float)(sx & 1) + 0.5f) * 0.5f) * bin_w;
                float vx = ((x > -1.0f) && (x < (float)W)) ? 1.0f : 0.0f;
                float xc = fminf(fmaxf(x, 0.0f), (float)(W - 1));
                int   x0 = (int)xc;
                float lx = xc - (float)x0;
                e = hi ? make_float2(__int_as_float(min(x0 + 1, W - 1)), lx * vx)
                       : make_float2(__int_as_float(x0), (1.0f - lx) * vx);
            }
            s_x[l] = e;
        }
    }
    __syncthreads();

    // ---------- hot loop ----------
    const int warpId = tid >> 5;
    const int wroi   = blockIdx.y * WARPS_PER_BLOCK + warpId;  // 0..63
    const int c0     = wroi * CH_PER_WARP;

    const float2 xe  = s_x[lane];
    const int    col = __float_as_int(xe.x);
    const float  wx  = xe.y;

    const float* pb   = feat + ((size_t)s_b * C + c0) * PLANE + col;
    float*       outp = out + ((size_t)r * C + c0) * (OUT_H * OUT_W);

    float vA[CH_PER_WARP], vB[CH_PER_WARP];
    float bacc[CH_PER_WARP];

    #pragma unroll
    for (int i = 0; i < NSAMP; ++i) {
        const float4 pe   = s_plan[i];    // warp-uniform
        const int    code = s_code[i];    // warp-uniform
        const int    offT = __float_as_int(pe.x);
        const int    offB = __float_as_int(pe.y);

        if (code == 2) {
            #pragma unroll
            for (int cc = 0; cc < CH_PER_WARP; ++cc)
                vA[cc] = __ldg(pb + (size_t)cc * PLANE + offT);
            #pragma unroll
            for (int cc = 0; cc < CH_PER_WARP; ++cc)
                vB[cc] = __ldg(pb + (size_t)cc * PLANE + offB);
        } else if (code == 1) {
            #pragma unroll
            for (int cc = 0; cc < CH_PER_WARP; ++cc) vA[cc] = vB[cc];
            #pragma unroll
            for (int cc = 0; cc < CH_PER_WARP; ++cc)
                vB[cc] = __ldg(pb + (size_t)cc * PLANE + offB);
        }
        // code 0: fully cached

        if ((i & 1) == 0) {
            #pragma unroll
            for (int cc = 0; cc < CH_PER_WARP; ++cc)
                bacc[cc] = pe.z * vA[cc] + pe.w * vB[cc];
        } else {
            #pragma unroll
            for (int cc = 0; cc < CH_PER_WARP; ++cc)
                bacc[cc] += pe.z * vA[cc] + pe.w * vB[cc];

            const int oy = i >> 1;
            #pragma unroll
            for (int cc = 0; cc < CH_PER_WARP; ++cc) {
                float v = wx * bacc[cc];
                v += __shfl_down_sync(0xffffffffu, v, 16);  // corner sum
                v += __shfl_down_sync(0xffffffffu, v, 1);   // x-pair sum
                if (lane < 14 && (lane & 1) == 0) {
                    outp[(size_t)cc * (OUT_H * OUT_W) + oy * OUT_W + (lane >> 1)] = v;
                }
            }
        }
    }
}

extern "C" void kernel_launch(void* const* d_in, const int* in_sizes, int n_in,
                              void* d_out, int out_size)
{
    const float* feat = (const float*)d_in[0];
    const float* rois = (const float*)d_in[1];
    float*       out  = (float*)d_out;

    dim3 grid(R, GROUPS);
    dim3 block(WARPS_PER_BLOCK * 32);
    roi_align_kernel<<<grid, block>>>(feat, rois, out);
}